// round 1
// baseline (speedup 1.0000x reference)
#include <cuda_runtime.h>

#define Bn 4
#define Nn 128
#define Cn 128
#define TFn 8
#define En 8192
#define NEGV (-1e9f)

// ---------------- scratch (static device globals; no allocation) ----------------
__device__ float g_msgE[Bn*Nn*Nn*Cn];         // dense e @ W_me, only edge slots valid (33.5MB)
__device__ float g_T1[Bn*Nn*Nn*TFn];          // te1 transposed: [b][dst][src][f]
__device__ float g_T2[Bn*Nn*Nn*TFn];          // te2 transposed: [b][dst][src][f]
__device__ float g_te3[Bn*Nn*Nn*TFn];         // te3 normal:     [b][src][dst][f]
__device__ float g_msg1[Bn*Nn*Cn];
__device__ float g_msg2[Bn*Nn*Cn];
__device__ float g_u1[Bn*Nn*Cn];
__device__ float g_t1[Bn*Nn*TFn];
__device__ float g_t2[Bn*Nn*TFn];
__device__ float g_t3[Bn*Nn*TFn];
__device__ float g_mgg[Bn*Cn];
__device__ float g_tg[Bn*TFn];
__device__ unsigned g_maxacc[Bn*Nn*Cn];

// ---------------- helpers ----------------
__device__ __forceinline__ unsigned fmap(float f) {
    int i = __float_as_int(f);
    return (i >= 0) ? ((unsigned)i | 0x80000000u) : ~(unsigned)i;
}
__device__ __forceinline__ float funmap(unsigned u) {
    int i = (u & 0x80000000u) ? (int)(u & 0x7FFFFFFFu) : ~(int)u;
    return __int_as_float(i);
}
__device__ __forceinline__ float brsum(float v, float* sred, int t) {
    #pragma unroll
    for (int o = 16; o; o >>= 1) v += __shfl_xor_sync(0xffffffffu, v, o);
    if ((t & 31) == 0) sred[t >> 5] = v;
    __syncthreads();
    v = sred[0] + sred[1] + sred[2] + sred[3];
    __syncthreads();
    return v;
}

// ---------------- K1: init / zero ----------------
// seg A: zero g_T1,g_T2,g_te3 (3*524288)
// seg B: zero g_msgE at edge slots (E*128)
// seg C: init g_maxacc to mapped(-1e9)
#define SEG_A (3*Bn*Nn*Nn*TFn)
#define SEG_B (En*Cn)
#define SEG_C (Bn*Nn*Cn)
__global__ void k_init(const int* __restrict__ eidx) {
    int idx = blockIdx.x * 256 + threadIdx.x;
    if (idx < SEG_A) {
        int per = Bn*Nn*Nn*TFn;
        if (idx < per)            g_T1[idx] = 0.f;
        else if (idx < 2*per)     g_T2[idx - per] = 0.f;
        else                      g_te3[idx - 2*per] = 0.f;
    } else if (idx < SEG_A + SEG_B) {
        int r = idx - SEG_A;
        int e = r >> 7, o = r & 127;
        int sg = eidx[e], dg = eidx[En + e];
        int b = sg >> 7, s = sg & 127, d = dg & 127;
        g_msgE[((((b*Nn + s)*Nn + d)) << 7) + o] = 0.f;
    } else if (idx < SEG_A + SEG_B + SEG_C) {
        g_maxacc[idx - SEG_A - SEG_B] = fmap(NEGV);
    }
}

// ---------------- K2: node & graph projections ----------------
__global__ void k_proj(const float* __restrict__ node, const float* __restrict__ graph,
                       const float* __restrict__ Wm1, const float* __restrict__ Wm2,
                       const float* __restrict__ Wu1,
                       const float* __restrict__ Wt1, const float* __restrict__ Wt2,
                       const float* __restrict__ Wt3,
                       const float* __restrict__ Wmg, const float* __restrict__ Wtg) {
    __shared__ float sx[128];
    int blk = blockIdx.x, t = threadIdx.x;
    if (blk < Bn*Nn) {
        sx[t] = node[blk*128 + t];
        __syncthreads();
        float a1 = 0.f, a2 = 0.f, a3 = 0.f;
        #pragma unroll 8
        for (int f = 0; f < 128; f++) {
            float x = sx[f];
            a1 += x * Wm1[f*128 + t];
            a2 += x * Wm2[f*128 + t];
            a3 += x * Wu1[f*128 + t];
        }
        g_msg1[blk*128 + t] = a1;
        g_msg2[blk*128 + t] = a2;
        g_u1[blk*128 + t]   = a3;
        if (t < 24) {
            int jj = t & 7;
            const float* W = (t < 8) ? Wt1 : ((t < 16) ? Wt2 : Wt3);
            float a = 0.f;
            #pragma unroll 8
            for (int f = 0; f < 128; f++) a += sx[f] * W[f*8 + jj];
            float* dstp = (t < 8) ? g_t1 : ((t < 16) ? g_t2 : g_t3);
            dstp[blk*8 + jj] = a;
        }
    } else {
        int g = blk - Bn*Nn;
        sx[t] = graph[g*128 + t];
        __syncthreads();
        float a = 0.f;
        #pragma unroll 8
        for (int f = 0; f < 128; f++) a += sx[f] * Wmg[f*128 + t];
        g_mgg[g*128 + t] = a;
        if (t < 8) {
            float bb = 0.f;
            #pragma unroll 8
            for (int f = 0; f < 128; f++) bb += sx[f] * Wtg[f*8 + t];
            g_tg[g*8 + t] = bb;
        }
    }
}

// ---------------- K3: per-edge projection + scatter-add ----------------
__global__ void k_scatter(const float* __restrict__ eattr, const int* __restrict__ eidx,
                          const float* __restrict__ Wme,
                          const float* __restrict__ Wte1, const float* __restrict__ Wte2,
                          const float* __restrict__ Wte3) {
    __shared__ float sa[128];
    int e = blockIdx.x, t = threadIdx.x;
    sa[t] = eattr[e*128 + t];
    __syncthreads();
    int sg = eidx[e], dg = eidx[En + e];
    int b = sg >> 7, s = sg & 127, d = dg & 127;
    int pos = (b*Nn + s)*Nn + d;
    float a = 0.f;
    #pragma unroll 8
    for (int f = 0; f < 128; f++) a += sa[f] * Wme[f*128 + t];
    atomicAdd(&g_msgE[pos*128 + t], a);
    if (t < 24) {
        int jj = t & 7;
        const float* W = (t < 8) ? Wte1 : ((t < 16) ? Wte2 : Wte3);
        float v = 0.f;
        #pragma unroll 8
        for (int f = 0; f < 128; f++) v += sa[f] * W[f*8 + jj];
        int posT = (b*Nn + d)*Nn + s;   // transposed layout for T1/T2
        if (t < 8)       atomicAdd(&g_T1[posT*8 + jj], v);
        else if (t < 16) atomicAdd(&g_T2[posT*8 + jj], v);
        else             atomicAdd(&g_te3[pos*8 + jj], v);
    }
}

// ---------------- K4: per-edge MPNN chain + atomic max ----------------
__global__ void k_mpnn(const int* __restrict__ eidx,
                       const float* __restrict__ ln1s, const float* __restrict__ ln1o,
                       const float* __restrict__ Wmlp1,
                       const float* __restrict__ ln2s, const float* __restrict__ ln2o,
                       const float* __restrict__ Wmlp2) {
    __shared__ float sy[128];
    __shared__ float sred[4];
    int e = blockIdx.x, t = threadIdx.x;
    int sg = eidx[e], dg = eidx[En + e];
    int b = sg >> 7, s = sg & 127, d = dg & 127;
    int pos = (b*Nn + s)*Nn + d;
    float x = g_msgE[pos*128 + t]
            + g_msg1[(b*Nn + d)*128 + t]
            + g_msg2[(b*Nn + s)*128 + t]
            + g_mgg[b*128 + t];
    const float* LNS[2] = { ln1s, ln2s };
    const float* LNO[2] = { ln1o, ln2o };
    const float* WM[2]  = { Wmlp1, Wmlp2 };
    #pragma unroll
    for (int r = 0; r < 2; r++) {
        float mean = brsum(x, sred, t) * (1.f/128.f);
        float dmu = x - mean;
        float var = brsum(dmu*dmu, sred, t) * (1.f/128.f);
        float y = LNS[r][t] * dmu * rsqrtf(var + 1e-5f) + LNO[r][t];
        y = fmaxf(y, 0.f);
        sy[t] = y;
        __syncthreads();
        float acc = 0.f;
        const float* W = WM[r];
        #pragma unroll 8
        for (int f = 0; f < 128; f++) acc += sy[f] * W[f*128 + t];
        __syncthreads();
        x = acc;
    }
    atomicMax(&g_maxacc[(b*Nn + d)*128 + t], fmap(x));
}

// ---------------- K5: per-edge triplet max + W_u3 ----------------
__global__ void k_tri(const int* __restrict__ eidx, const float* __restrict__ Wu3,
                      float* __restrict__ out2) {
    __shared__ float sw[4][8];
    __shared__ float stm[8];
    int e = blockIdx.x, t = threadIdx.x;
    int sg = eidx[e], dg = eidx[En + e];
    int b = sg >> 7, j = sg & 127, k = dg & 127;
    int i = t;
    const float4* t1v = (const float4*)g_t1;
    const float4* T1v = (const float4*)g_T1;
    const float4* T2v = (const float4*)g_T2;
    int ia = (b*Nn + i) * 2;
    int i1 = ((b*Nn + j)*Nn + i) * 2;   // te1[b,i,j] stored [b][j][i]
    int i2 = ((b*Nn + k)*Nn + i) * 2;   // te2[b,i,k] stored [b][k][i]
    float4 a0 = t1v[ia],   a1 = t1v[ia+1];
    float4 b0 = T1v[i1],   b1 = T1v[i1+1];
    float4 c0 = T2v[i2],   c1 = T2v[i2+1];
    float v[8];
    v[0] = a0.x + b0.x + c0.x;  v[1] = a0.y + b0.y + c0.y;
    v[2] = a0.z + b0.z + c0.z;  v[3] = a0.w + b0.w + c0.w;
    v[4] = a1.x + b1.x + c1.x;  v[5] = a1.y + b1.y + c1.y;
    v[6] = a1.z + b1.z + c1.z;  v[7] = a1.w + b1.w + c1.w;
    #pragma unroll
    for (int off = 16; off; off >>= 1) {
        #pragma unroll
        for (int f = 0; f < 8; f++)
            v[f] = fmaxf(v[f], __shfl_xor_sync(0xffffffffu, v[f], off));
    }
    if ((t & 31) == 0) {
        int w = t >> 5;
        #pragma unroll
        for (int f = 0; f < 8; f++) sw[w][f] = v[f];
    }
    __syncthreads();
    if (t < 8) {
        float m = fmaxf(fmaxf(sw[0][t], sw[1][t]), fmaxf(sw[2][t], sw[3][t]));
        m += g_t2[(b*Nn + j)*8 + t] + g_t3[(b*Nn + k)*8 + t]
           + g_te3[((b*Nn + j)*Nn + k)*8 + t] + g_tg[b*8 + t];
        stm[t] = m;
    }
    __syncthreads();
    float acc = 0.f;
    #pragma unroll
    for (int f = 0; f < 8; f++) acc += stm[f] * Wu3[f*128 + t];
    out2[e*128 + t] = fmaxf(acc, 0.f);
}

// ---------------- K6: final ret = LN(u1 + max @ W_u2) ----------------
__global__ void k_final(const float* __restrict__ Wu2,
                        const float* __restrict__ lnfs, const float* __restrict__ lnfo,
                        float* __restrict__ out1) {
    __shared__ float sm[128];
    __shared__ float sred[4];
    int n = blockIdx.x, t = threadIdx.x;
    sm[t] = funmap(g_maxacc[n*128 + t]);
    __syncthreads();
    float acc = g_u1[n*128 + t];
    #pragma unroll 8
    for (int f = 0; f < 128; f++) acc += sm[f] * Wu2[f*128 + t];
    float mean = brsum(acc, sred, t) * (1.f/128.f);
    float dmu = acc - mean;
    float var = brsum(dmu*dmu, sred, t) * (1.f/128.f);
    out1[n*128 + t] = lnfs[t] * dmu * rsqrtf(var + 1e-5f) + lnfo[t];
}

// ---------------- launch ----------------
extern "C" void kernel_launch(void* const* d_in, const int* in_sizes, int n_in,
                              void* d_out, int out_size) {
    const float* node_fts  = (const float*)d_in[0];
    const float* edge_attr = (const float*)d_in[1];
    const float* graph_fts = (const float*)d_in[2];
    const float* W_tri1 = (const float*)d_in[3];
    const float* W_tri2 = (const float*)d_in[4];
    const float* W_tri3 = (const float*)d_in[5];
    const float* W_te1  = (const float*)d_in[6];
    const float* W_te2  = (const float*)d_in[7];
    const float* W_te3  = (const float*)d_in[8];
    const float* W_tg   = (const float*)d_in[9];
    const float* W_m1   = (const float*)d_in[10];
    const float* W_m2   = (const float*)d_in[11];
    const float* W_me   = (const float*)d_in[12];
    const float* W_mg   = (const float*)d_in[13];
    const float* ln1_s  = (const float*)d_in[14];
    const float* ln1_o  = (const float*)d_in[15];
    const float* W_mlp1 = (const float*)d_in[16];
    const float* ln2_s  = (const float*)d_in[17];
    const float* ln2_o  = (const float*)d_in[18];
    const float* W_mlp2 = (const float*)d_in[19];
    const float* W_u1   = (const float*)d_in[20];
    const float* W_u2   = (const float*)d_in[21];
    const float* W_u3   = (const float*)d_in[22];
    const float* lnf_s  = (const float*)d_in[23];
    const float* lnf_o  = (const float*)d_in[24];
    const int*   eidx   = (const int*)d_in[25];
    // d_in[26] = batch (derivable: node_id >> 7)

    float* out1 = (float*)d_out;                 // ret      [512,128]
    float* out2 = out1 + Bn*Nn*Cn;               // tri gath [8192,128]

    int init_total = SEG_A + SEG_B + SEG_C;
    k_init<<<(init_total + 255)/256, 256>>>(eidx);
    k_proj<<<Bn*Nn + Bn, 128>>>(node_fts, graph_fts, W_m1, W_m2, W_u1,
                                W_tri1, W_tri2, W_tri3, W_mg, W_tg);
    k_scatter<<<En, 128>>>(edge_attr, eidx, W_me, W_te1, W_te2, W_te3);
    k_mpnn<<<En, 128>>>(eidx, ln1_s, ln1_o, W_mlp1, ln2_s, ln2_o, W_mlp2);
    k_tri<<<En, 128>>>(eidx, W_u3, out2);
    k_final<<<Bn*Nn, 128>>>(W_u2, lnf_s, lnf_o, out1);
}

// round 2
// speedup vs baseline: 1.4958x; 1.4958x over previous
#include <cuda_runtime.h>

#define Bn 4
#define Nn 128
#define Cn 128
#define TFn 8
#define En 8192
#define NEGV (-1e9f)
#define ROWS 32   // edges per block in GEMM kernels

// ---------------- scratch (static device globals; no allocation) ----------------
__device__ float g_msgE[Bn*Nn*Nn*Cn];         // dense e @ W_me, only edge slots valid
__device__ float g_T1[Bn*Nn*Nn*TFn];          // te1 transposed: [b][dst][src][f]
__device__ float g_T2[Bn*Nn*Nn*TFn];          // te2 transposed: [b][dst][src][f]
__device__ float g_te3[Bn*Nn*Nn*TFn];         // te3 normal:     [b][src][dst][f]
__device__ float g_msg1[Bn*Nn*Cn];
__device__ float g_msg2[Bn*Nn*Cn];
__device__ float g_u1[Bn*Nn*Cn];
__device__ float g_t1[Bn*Nn*TFn];
__device__ float g_t2[Bn*Nn*TFn];
__device__ float g_t3[Bn*Nn*TFn];
__device__ float g_mgg[Bn*Cn];
__device__ float g_tg[Bn*TFn];
__device__ unsigned g_maxacc[Bn*Nn*Cn];

// ---------------- helpers ----------------
__device__ __forceinline__ unsigned fmap(float f) {
    int i = __float_as_int(f);
    return (i >= 0) ? ((unsigned)i | 0x80000000u) : ~(unsigned)i;
}
__device__ __forceinline__ float funmap(unsigned u) {
    int i = (u & 0x80000000u) ? (int)(u & 0x7FFFFFFFu) : ~(int)u;
    return __int_as_float(i);
}
__device__ __forceinline__ float wredsum(float v) {
    #pragma unroll
    for (int o = 16; o; o >>= 1) v += __shfl_xor_sync(0xffffffffu, v, o);
    return v;
}
__device__ __forceinline__ float brsum(float v, float* sred, int t) {
    v = wredsum(v);
    if ((t & 31) == 0) sred[t >> 5] = v;
    __syncthreads();
    v = sred[0] + sred[1] + sred[2] + sred[3];
    __syncthreads();
    return v;
}

// ---------------- K1: init / zero ----------------
#define SEG_A (3*Bn*Nn*Nn*TFn)
#define SEG_B (En*Cn)
#define SEG_C (Bn*Nn*Cn)
__global__ void k_init(const int* __restrict__ eidx) {
    int idx = blockIdx.x * 256 + threadIdx.x;
    if (idx < SEG_A) {
        int per = Bn*Nn*Nn*TFn;
        if (idx < per)            g_T1[idx] = 0.f;
        else if (idx < 2*per)     g_T2[idx - per] = 0.f;
        else                      g_te3[idx - 2*per] = 0.f;
    } else if (idx < SEG_A + SEG_B) {
        int r = idx - SEG_A;
        int e = r >> 7, o = r & 127;
        int sg = eidx[e], dg = eidx[En + e];
        int b = sg >> 7, s = sg & 127, d = dg & 127;
        g_msgE[((((b*Nn + s)*Nn + d)) << 7) + o] = 0.f;
    } else if (idx < SEG_A + SEG_B + SEG_C) {
        g_maxacc[idx - SEG_A - SEG_B] = fmap(NEGV);
    }
}

// ---------------- K2: node & graph projections ----------------
__global__ void k_proj(const float* __restrict__ node, const float* __restrict__ graph,
                       const float* __restrict__ Wm1, const float* __restrict__ Wm2,
                       const float* __restrict__ Wu1,
                       const float* __restrict__ Wt1, const float* __restrict__ Wt2,
                       const float* __restrict__ Wt3,
                       const float* __restrict__ Wmg, const float* __restrict__ Wtg) {
    __shared__ float sx[128];
    int blk = blockIdx.x, t = threadIdx.x;
    if (blk < Bn*Nn) {
        sx[t] = node[blk*128 + t];
        __syncthreads();
        float a1 = 0.f, a2 = 0.f, a3 = 0.f;
        #pragma unroll 8
        for (int f = 0; f < 128; f++) {
            float x = sx[f];
            a1 += x * Wm1[f*128 + t];
            a2 += x * Wm2[f*128 + t];
            a3 += x * Wu1[f*128 + t];
        }
        g_msg1[blk*128 + t] = a1;
        g_msg2[blk*128 + t] = a2;
        g_u1[blk*128 + t]   = a3;
        if (t < 24) {
            int jj = t & 7;
            const float* W = (t < 8) ? Wt1 : ((t < 16) ? Wt2 : Wt3);
            float a = 0.f;
            #pragma unroll 8
            for (int f = 0; f < 128; f++) a += sx[f] * W[f*8 + jj];
            float* dstp = (t < 8) ? g_t1 : ((t < 16) ? g_t2 : g_t3);
            dstp[blk*8 + jj] = a;
        }
    } else {
        int g = blk - Bn*Nn;
        sx[t] = graph[g*128 + t];
        __syncthreads();
        float a = 0.f;
        #pragma unroll 8
        for (int f = 0; f < 128; f++) a += sx[f] * Wmg[f*128 + t];
        g_mgg[g*128 + t] = a;
        if (t < 8) {
            float bb = 0.f;
            #pragma unroll 8
            for (int f = 0; f < 128; f++) bb += sx[f] * Wtg[f*8 + t];
            g_tg[g*8 + t] = bb;
        }
    }
}

// ---------------- K3: edge projections as register-tiled GEMM + scatter-add ----------------
// grid = En/ROWS blocks of 256 threads. Warp w owns rows w*4 .. w*4+3.
__global__ void k_scatter(const float* __restrict__ eattr, const int* __restrict__ eidx,
                          const float* __restrict__ Wme,
                          const float* __restrict__ Wte1, const float* __restrict__ Wte2,
                          const float* __restrict__ Wte3) {
    __shared__ float sA[ROWS][128];
    int t = threadIdx.x, warp = t >> 5, lane = t & 31;
    int e0 = blockIdx.x * ROWS;
    int posMain[4], posT[4];
    #pragma unroll
    for (int i = 0; i < 4; i++) {
        int r = warp*4 + i, e = e0 + r;
        *(float4*)&sA[r][lane*4] = *(const float4*)&eattr[e*128 + lane*4];
        int sg = eidx[e], dg = eidx[En + e];
        int b = sg >> 7, s = sg & 127, d = dg & 127;
        posMain[i] = (b*Nn + s)*Nn + d;
        posT[i]    = (b*Nn + d)*Nn + s;
    }
    __syncwarp();
    // main GEMM: 4 rows x (4 cols at lane*4) per thread
    float acc[4][4] = {};
    #pragma unroll 4
    for (int k = 0; k < 128; k += 4) {
        float4 b0 = *(const float4*)&Wme[(k+0)*128 + lane*4];
        float4 b1 = *(const float4*)&Wme[(k+1)*128 + lane*4];
        float4 b2 = *(const float4*)&Wme[(k+2)*128 + lane*4];
        float4 b3 = *(const float4*)&Wme[(k+3)*128 + lane*4];
        #pragma unroll
        for (int i = 0; i < 4; i++) {
            float4 a = *(const float4*)&sA[warp*4 + i][k];
            acc[i][0] += a.x*b0.x + a.y*b1.x + a.z*b2.x + a.w*b3.x;
            acc[i][1] += a.x*b0.y + a.y*b1.y + a.z*b2.y + a.w*b3.y;
            acc[i][2] += a.x*b0.z + a.y*b1.z + a.z*b2.z + a.w*b3.z;
            acc[i][3] += a.x*b0.w + a.y*b1.w + a.z*b2.w + a.w*b3.w;
        }
    }
    #pragma unroll
    for (int i = 0; i < 4; i++) {
        float* dst = &g_msgE[posMain[i]*128 + lane*4];
        atomicAdd(dst + 0, acc[i][0]);
        atomicAdd(dst + 1, acc[i][1]);
        atomicAdd(dst + 2, acc[i][2]);
        atomicAdd(dst + 3, acc[i][3]);
    }
    // te projections: lanes 0..23, one col each, 4 rows
    if (lane < 24) {
        const float* W = (lane < 8) ? Wte1 : ((lane < 16) ? Wte2 : Wte3);
        int c = lane & 7;
        float acc2[4] = {};
        #pragma unroll 4
        for (int k = 0; k < 128; k += 4) {
            float w0 = W[(k+0)*8 + c], w1 = W[(k+1)*8 + c];
            float w2 = W[(k+2)*8 + c], w3 = W[(k+3)*8 + c];
            #pragma unroll
            for (int i = 0; i < 4; i++) {
                float4 a = *(const float4*)&sA[warp*4 + i][k];
                acc2[i] += a.x*w0 + a.y*w1 + a.z*w2 + a.w*w3;
            }
        }
        #pragma unroll
        for (int i = 0; i < 4; i++) {
            if (lane < 8)       atomicAdd(&g_T1[posT[i]*8 + c], acc2[i]);
            else if (lane < 16) atomicAdd(&g_T2[posT[i]*8 + c], acc2[i]);
            else                atomicAdd(&g_te3[posMain[i]*8 + c], acc2[i]);
        }
    }
}

// ---------------- K4: fused gather+LN1+GEMM1+LN2+GEMM2+atomicMax ----------------
// grid = En/ROWS blocks of 256 threads. Warp w exclusively owns rows w*4..w*4+3
// through all stages -> no __syncthreads needed, only __syncwarp.
__global__ void k_mpnn(const int* __restrict__ eidx,
                       const float* __restrict__ ln1s, const float* __restrict__ ln1o,
                       const float* __restrict__ W1,
                       const float* __restrict__ ln2s, const float* __restrict__ ln2o,
                       const float* __restrict__ W2) {
    __shared__ float sY[ROWS][128];
    int t = threadIdx.x, warp = t >> 5, lane = t & 31;
    int e0 = blockIdx.x * ROWS;
    int dglob[4];
    float4 s1 = *(const float4*)&ln1s[lane*4];
    float4 o1 = *(const float4*)&ln1o[lane*4];
    // ---- stage 1: gather + LN1 + ReLU ----
    #pragma unroll
    for (int i = 0; i < 4; i++) {
        int r = warp*4 + i, e = e0 + r;
        int sg = eidx[e], dg = eidx[En + e];
        int b = sg >> 7, s = sg & 127, d = dg & 127;
        dglob[i] = b*Nn + d;
        float4 x  = *(const float4*)&g_msgE[((b*Nn + s)*Nn + d)*128 + lane*4];
        float4 m1 = *(const float4*)&g_msg1[dglob[i]*128 + lane*4];
        float4 m2 = *(const float4*)&g_msg2[(b*Nn + s)*128 + lane*4];
        float4 mg = *(const float4*)&g_mgg[b*128 + lane*4];
        x.x += m1.x + m2.x + mg.x;
        x.y += m1.y + m2.y + mg.y;
        x.z += m1.z + m2.z + mg.z;
        x.w += m1.w + m2.w + mg.w;
        float mean = wredsum(x.x + x.y + x.z + x.w) * (1.f/128.f);
        float dx = x.x - mean, dy = x.y - mean, dz = x.z - mean, dw = x.w - mean;
        float var = wredsum(dx*dx + dy*dy + dz*dz + dw*dw) * (1.f/128.f);
        float rstd = rsqrtf(var + 1e-5f);
        float4 y;
        y.x = fmaxf(s1.x * dx * rstd + o1.x, 0.f);
        y.y = fmaxf(s1.y * dy * rstd + o1.y, 0.f);
        y.z = fmaxf(s1.z * dz * rstd + o1.z, 0.f);
        y.w = fmaxf(s1.w * dw * rstd + o1.w, 0.f);
        *(float4*)&sY[r][lane*4] = y;
    }
    __syncwarp();
    // ---- stage 2: GEMM1 (Y @ W1) + LN2 + ReLU, write back to sY ----
    float4 s2 = *(const float4*)&ln2s[lane*4];
    float4 o2 = *(const float4*)&ln2o[lane*4];
    {
        float acc[4][4] = {};
        #pragma unroll 4
        for (int k = 0; k < 128; k += 4) {
            float4 b0 = *(const float4*)&W1[(k+0)*128 + lane*4];
            float4 b1 = *(const float4*)&W1[(k+1)*128 + lane*4];
            float4 b2 = *(const float4*)&W1[(k+2)*128 + lane*4];
            float4 b3 = *(const float4*)&W1[(k+3)*128 + lane*4];
            #pragma unroll
            for (int i = 0; i < 4; i++) {
                float4 a = *(const float4*)&sY[warp*4 + i][k];
                acc[i][0] += a.x*b0.x + a.y*b1.x + a.z*b2.x + a.w*b3.x;
                acc[i][1] += a.x*b0.y + a.y*b1.y + a.z*b2.y + a.w*b3.y;
                acc[i][2] += a.x*b0.z + a.y*b1.z + a.z*b2.z + a.w*b3.z;
                acc[i][3] += a.x*b0.w + a.y*b1.w + a.z*b2.w + a.w*b3.w;
            }
        }
        __syncwarp();
        #pragma unroll
        for (int i = 0; i < 4; i++) {
            float mean = wredsum(acc[i][0] + acc[i][1] + acc[i][2] + acc[i][3]) * (1.f/128.f);
            float d0 = acc[i][0] - mean, d1 = acc[i][1] - mean;
            float d2 = acc[i][2] - mean, d3 = acc[i][3] - mean;
            float var = wredsum(d0*d0 + d1*d1 + d2*d2 + d3*d3) * (1.f/128.f);
            float rstd = rsqrtf(var + 1e-5f);
            float4 y;
            y.x = fmaxf(s2.x * d0 * rstd + o2.x, 0.f);
            y.y = fmaxf(s2.y * d1 * rstd + o2.y, 0.f);
            y.z = fmaxf(s2.z * d2 * rstd + o2.z, 0.f);
            y.w = fmaxf(s2.w * d3 * rstd + o2.w, 0.f);
            *(float4*)&sY[warp*4 + i][lane*4] = y;
        }
    }
    __syncwarp();
    // ---- stage 3: GEMM2 (Y2 @ W2) + atomicMax epilogue ----
    {
        float acc[4][4] = {};
        #pragma unroll 4
        for (int k = 0; k < 128; k += 4) {
            float4 b0 = *(const float4*)&W2[(k+0)*128 + lane*4];
            float4 b1 = *(const float4*)&W2[(k+1)*128 + lane*4];
            float4 b2 = *(const float4*)&W2[(k+2)*128 + lane*4];
            float4 b3 = *(const float4*)&W2[(k+3)*128 + lane*4];
            #pragma unroll
            for (int i = 0; i < 4; i++) {
                float4 a = *(const float4*)&sY[warp*4 + i][k];
                acc[i][0] += a.x*b0.x + a.y*b1.x + a.z*b2.x + a.w*b3.x;
                acc[i][1] += a.x*b0.y + a.y*b1.y + a.z*b2.y + a.w*b3.y;
                acc[i][2] += a.x*b0.z + a.y*b1.z + a.z*b2.z + a.w*b3.z;
                acc[i][3] += a.x*b0.w + a.y*b1.w + a.z*b2.w + a.w*b3.w;
            }
        }
        #pragma unroll
        for (int i = 0; i < 4; i++) {
            unsigned* dst = &g_maxacc[dglob[i]*128 + lane*4];
            atomicMax(dst + 0, fmap(acc[i][0]));
            atomicMax(dst + 1, fmap(acc[i][1]));
            atomicMax(dst + 2, fmap(acc[i][2]));
            atomicMax(dst + 3, fmap(acc[i][3]));
        }
    }
}

// ---------------- K5: per-edge triplet max + W_u3 ----------------
__global__ void k_tri(const int* __restrict__ eidx, const float* __restrict__ Wu3,
                      float* __restrict__ out2) {
    __shared__ float sw[4][8];
    __shared__ float stm[8];
    int e = blockIdx.x, t = threadIdx.x;
    int sg = eidx[e], dg = eidx[En + e];
    int b = sg >> 7, j = sg & 127, k = dg & 127;
    int i = t;
    const float4* t1v = (const float4*)g_t1;
    const float4* T1v = (const float4*)g_T1;
    const float4* T2v = (const float4*)g_T2;
    int ia = (b*Nn + i) * 2;
    int i1 = ((b*Nn + j)*Nn + i) * 2;
    int i2 = ((b*Nn + k)*Nn + i) * 2;
    float4 a0 = t1v[ia],   a1 = t1v[ia+1];
    float4 b0 = T1v[i1],   b1 = T1v[i1+1];
    float4 c0 = T2v[i2],   c1 = T2v[i2+1];
    float v[8];
    v[0] = a0.x + b0.x + c0.x;  v[1] = a0.y + b0.y + c0.y;
    v[2] = a0.z + b0.z + c0.z;  v[3] = a0.w + b0.w + c0.w;
    v[4] = a1.x + b1.x + c1.x;  v[5] = a1.y + b1.y + c1.y;
    v[6] = a1.z + b1.z + c1.z;  v[7] = a1.w + b1.w + c1.w;
    #pragma unroll
    for (int off = 16; off; off >>= 1) {
        #pragma unroll
        for (int f = 0; f < 8; f++)
            v[f] = fmaxf(v[f], __shfl_xor_sync(0xffffffffu, v[f], off));
    }
    if ((t & 31) == 0) {
        int w = t >> 5;
        #pragma unroll
        for (int f = 0; f < 8; f++) sw[w][f] = v[f];
    }
    __syncthreads();
    if (t < 8) {
        float m = fmaxf(fmaxf(sw[0][t], sw[1][t]), fmaxf(sw[2][t], sw[3][t]));
        m += g_t2[(b*Nn + j)*8 + t] + g_t3[(b*Nn + k)*8 + t]
           + g_te3[((b*Nn + j)*Nn + k)*8 + t] + g_tg[b*8 + t];
        stm[t] = m;
    }
    __syncthreads();
    float acc = 0.f;
    #pragma unroll
    for (int f = 0; f < 8; f++) acc += stm[f] * Wu3[f*128 + t];
    out2[e*128 + t] = fmaxf(acc, 0.f);
}

// ---------------- K6: final ret = LN(u1 + max @ W_u2) ----------------
__global__ void k_final(const float* __restrict__ Wu2,
                        const float* __restrict__ lnfs, const float* __restrict__ lnfo,
                        float* __restrict__ out1) {
    __shared__ float sm[128];
    __shared__ float sred[4];
    int n = blockIdx.x, t = threadIdx.x;
    sm[t] = funmap(g_maxacc[n*128 + t]);
    __syncthreads();
    float acc = g_u1[n*128 + t];
    #pragma unroll 8
    for (int f = 0; f < 128; f++) acc += sm[f] * Wu2[f*128 + t];
    float mean = brsum(acc, sred, t) * (1.f/128.f);
    float dmu = acc - mean;
    float var = brsum(dmu*dmu, sred, t) * (1.f/128.f);
    out1[n*128 + t] = lnfs[t] * dmu * rsqrtf(var + 1e-5f) + lnfo[t];
}

// ---------------- launch ----------------
extern "C" void kernel_launch(void* const* d_in, const int* in_sizes, int n_in,
                              void* d_out, int out_size) {
    const float* node_fts  = (const float*)d_in[0];
    const float* edge_attr = (const float*)d_in[1];
    const float* graph_fts = (const float*)d_in[2];
    const float* W_tri1 = (const float*)d_in[3];
    const float* W_tri2 = (const float*)d_in[4];
    const float* W_tri3 = (const float*)d_in[5];
    const float* W_te1  = (const float*)d_in[6];
    const float* W_te2  = (const float*)d_in[7];
    const float* W_te3  = (const float*)d_in[8];
    const float* W_tg   = (const float*)d_in[9];
    const float* W_m1   = (const float*)d_in[10];
    const float* W_m2   = (const float*)d_in[11];
    const float* W_me   = (const float*)d_in[12];
    const float* W_mg   = (const float*)d_in[13];
    const float* ln1_s  = (const float*)d_in[14];
    const float* ln1_o  = (const float*)d_in[15];
    const float* W_mlp1 = (const float*)d_in[16];
    const float* ln2_s  = (const float*)d_in[17];
    const float* ln2_o  = (const float*)d_in[18];
    const float* W_mlp2 = (const float*)d_in[19];
    const float* W_u1   = (const float*)d_in[20];
    const float* W_u2   = (const float*)d_in[21];
    const float* W_u3   = (const float*)d_in[22];
    const float* lnf_s  = (const float*)d_in[23];
    const float* lnf_o  = (const float*)d_in[24];
    const int*   eidx   = (const int*)d_in[25];

    float* out1 = (float*)d_out;                 // ret      [512,128]
    float* out2 = out1 + Bn*Nn*Cn;               // tri gath [8192,128]

    int init_total = SEG_A + SEG_B + SEG_C;
    k_init<<<(init_total + 255)/256, 256>>>(eidx);
    k_proj<<<Bn*Nn + Bn, 128>>>(node_fts, graph_fts, W_m1, W_m2, W_u1,
                                W_tri1, W_tri2, W_tri3, W_mg, W_tg);
    k_scatter<<<En/ROWS, 256>>>(edge_attr, eidx, W_me, W_te1, W_te2, W_te3);
    k_mpnn<<<En/ROWS, 256>>>(eidx, ln1_s, ln1_o, W_mlp1, ln2_s, ln2_o, W_mlp2);
    k_tri<<<En, 128>>>(eidx, W_u3, out2);
    k_final<<<Bn*Nn, 128>>>(W_u2, lnf_s, lnf_o, out1);
}